// round 1
// baseline (speedup 1.0000x reference)
#include <cuda_runtime.h>
#include <cstdint>

// Scratch: 8 batches x 2^22 floats = 128 MB (allowed: __device__ global)
static __device__ float g_work[(size_t)8 * 4194304];
static __device__ float g_y[8 * 1024];

#define FULLMASK 0xffffffffu
#define PADN 4194304
#define OUTN 4000000

// Warp-level WHT over (32 * NREG) elements: position = j*32 + lane.
// Ascending stage order (h=1,2,4,...) to match the reference's op order.
template<int NREG>
__device__ __forceinline__ void wht_warp(float* e, int lane) {
  // lane-bit stages: h = 1..16 via shfl.xor
#pragma unroll
  for (int h = 1; h <= 16; h <<= 1) {
    const float sg = (lane & h) ? -1.0f : 1.0f;
#pragma unroll
    for (int j = 0; j < NREG; j++) {
      float p = __shfl_xor_sync(FULLMASK, e[j], h);
      // bit clear: e+p ; bit set: p-e. fma(+-1, e, p) rounds identically.
      e[j] = fmaf(sg, e[j], p);
    }
  }
  // register-bit stages: h = 32, 64, ... (pairs j, j|m)
#pragma unroll
  for (int m = 1; m < NREG; m <<= 1) {
#pragma unroll
    for (int j = 0; j < NREG; j++) {
      if ((j & m) == 0) {
        float a = e[j], b = e[j | m];
        e[j] = a + b;
        e[j | m] = a - b;
      }
    }
  }
}

// Kernel 1: y[b] = WHT_1024(x[b] * B[0:1024]).  8 warps, warp per batch.
__global__ void __launch_bounds__(256) k_y(const float* __restrict__ x,
                                           const float* __restrict__ B) {
  const int w = threadIdx.x >> 5;  // batch
  const int l = threadIdx.x & 31;
  float e[32];
#pragma unroll
  for (int j = 0; j < 32; j++) {
    int i = j * 32 + l;
    e[j] = x[w * 1024 + i] * B[i];
  }
  wht_warp<32>(e, l);
#pragma unroll
  for (int j = 0; j < 32; j++) g_y[w * 1024 + j * 32 + l] = e[j];
}

// Pass A: per contiguous 2048-chunk: gather t = y[Pi&1023]*G, then 2048-pt WHT
// (stages h=1..1024 of the full transform). Warp w handles batch w.
__global__ void __launch_bounds__(256) k_passA(const float* __restrict__ G,
                                               const int* __restrict__ Pi) {
  __shared__ float s_y[8 * 1024];          // 32 KB
  __shared__ float s_g[2048];              // 8 KB
  __shared__ unsigned short s_pi[2048];    // 4 KB  -> 44 KB static total
  const int tid = threadIdx.x;
  const size_t base = (size_t)blockIdx.x * 2048;

#pragma unroll
  for (int i = tid; i < 2048; i += 256) {
    s_g[i] = G[base + i];
    s_pi[i] = (unsigned short)(Pi[base + i] & 1023);
  }
#pragma unroll
  for (int i = tid; i < 8192; i += 256) s_y[i] = g_y[i];
  __syncthreads();

  const int w = tid >> 5, l = tid & 31;
  const float* yb = s_y + w * 1024;
  float e[64];
#pragma unroll
  for (int j = 0; j < 64; j++) {
    int i = j * 32 + l;
    e[j] = yb[s_pi[i]] * s_g[i];
  }
  wht_warp<64>(e, l);
  float* o = g_work + (size_t)w * PADN + base;
#pragma unroll
  for (int j = 0; j < 64; j++) o[j * 32 + l] = e[j];
}

// Pass B: 2048-pt WHT along the row dimension (stride 2048), i.e. stages
// h=2048..2^21 of the full transform. Tile = 2048 rows x 8 cols, XOR-swizzled
// smem layout addr = c*2048 + (r ^ (c<<2)) : conflict-free for both the
// row-major staging and the warp-per-column transform. Output fused with *S
// and truncation to 4,000,000 elements.
__global__ void __launch_bounds__(256) k_passB(const float* __restrict__ S,
                                               float* __restrict__ out) {
  extern __shared__ float tile[];  // 2048 * 8 floats = 64 KB (dynamic)
  const int tid = threadIdx.x;
  const int b = blockIdx.y;
  const int c0 = blockIdx.x * 8;
  const float* wrk = g_work + (size_t)b * PADN;

  // stage in: float4 loads -> 32B sectors fully used on the strided reads
  for (int idx = tid; idx < 4096; idx += 256) {
    int r = idx >> 1;
    int cq = (idx & 1) * 4;
    float4 v = *(const float4*)(wrk + (size_t)r * 2048 + c0 + cq);
    tile[(cq + 0) * 2048 + (r ^ ((cq + 0) << 2))] = v.x;
    tile[(cq + 1) * 2048 + (r ^ ((cq + 1) << 2))] = v.y;
    tile[(cq + 2) * 2048 + (r ^ ((cq + 2) << 2))] = v.z;
    tile[(cq + 3) * 2048 + (r ^ ((cq + 3) << 2))] = v.w;
  }
  __syncthreads();

  const int w = tid >> 5, l = tid & 31;
  const int c4 = w << 2;
  float* col = tile + w * 2048;
  float e[64];
#pragma unroll
  for (int j = 0; j < 64; j++) e[j] = col[j * 32 + (l ^ c4)];
  wht_warp<64>(e, l);
#pragma unroll
  for (int j = 0; j < 64; j++) col[j * 32 + (l ^ c4)] = e[j];
  __syncthreads();

  // stage out with *S and truncation to OUTN (OUTN % 4 == 0, float4-aligned)
  for (int idx = tid; idx < 4096; idx += 256) {
    int r = idx >> 1;
    int cq = (idx & 1) * 4;
    int k = r * 2048 + c0 + cq;
    if (k < OUTN) {
      float4 s4 = *(const float4*)(S + k);
      float4 v;
      v.x = tile[(cq + 0) * 2048 + (r ^ ((cq + 0) << 2))] * s4.x;
      v.y = tile[(cq + 1) * 2048 + (r ^ ((cq + 1) << 2))] * s4.y;
      v.z = tile[(cq + 2) * 2048 + (r ^ ((cq + 2) << 2))] * s4.z;
      v.w = tile[(cq + 3) * 2048 + (r ^ ((cq + 3) << 2))] * s4.w;
      *(float4*)(out + (size_t)b * OUTN + k) = v;
    }
  }
}

extern "C" void kernel_launch(void* const* d_in, const int* in_sizes, int n_in,
                              void* d_out, int out_size) {
  const float* x = (const float*)d_in[0];
  const float* B = (const float*)d_in[1];
  const float* G = (const float*)d_in[2];
  const float* S = (const float*)d_in[3];
  const int* Pi = (const int*)d_in[4];
  float* out = (float*)d_out;

  cudaFuncSetAttribute(k_passB, cudaFuncAttributeMaxDynamicSharedMemorySize,
                       65536);

  k_y<<<1, 256>>>(x, B);
  k_passA<<<2048, 256>>>(G, Pi);
  k_passB<<<dim3(256, 8), 256, 65536>>>(S, out);
}

// round 2
// speedup vs baseline: 1.0126x; 1.0126x over previous
#include <cuda_runtime.h>
#include <cuda_fp16.h>
#include <cstdint>

#define FULLMASK 0xffffffffu
#define PADN 4194304
#define OUTN 4000000

// fp16 scratch: 8 batches x 2^22 halves = 64 MB
static __device__ __half g_work[(size_t)8 * PADN];
static __device__ float g_y[8 * 1024];

// Warp-level WHT over (32*NREG) elements, position = j*32 + lane.
template<int NREG>
__device__ __forceinline__ void wht_warp(float* e, int lane) {
#pragma unroll
  for (int h = 1; h <= 16; h <<= 1) {
    const float sg = (lane & h) ? -1.0f : 1.0f;
#pragma unroll
    for (int j = 0; j < NREG; j++) {
      float p = __shfl_xor_sync(FULLMASK, e[j], h);
      e[j] = fmaf(sg, e[j], p);
    }
  }
#pragma unroll
  for (int m = 1; m < NREG; m <<= 1) {
#pragma unroll
    for (int j = 0; j < NREG; j++) {
      if ((j & m) == 0) {
        float a = e[j], b = e[j | m];
        e[j] = a + b;
        e[j | m] = a - b;
      }
    }
  }
}

// Kernel 1: y[b] = WHT_1024(x[b] * B[0:1024]). 8 warps, warp per batch.
__global__ void __launch_bounds__(256) k_y(const float* __restrict__ x,
                                           const float* __restrict__ B) {
  const int w = threadIdx.x >> 5;
  const int l = threadIdx.x & 31;
  float e[32];
#pragma unroll
  for (int j = 0; j < 32; j++) {
    int i = j * 32 + l;
    e[j] = x[w * 1024 + i] * B[i];
  }
  wht_warp<32>(e, l);
#pragma unroll
  for (int j = 0; j < 32; j++) g_y[w * 1024 + j * 32 + l] = e[j];
}

// Pass A: gather t = y[Pi&1023]*G per 2048-chunk, 2048-pt WHT (stages h=1..1024),
// store fp16 scratch. Warp w = batch w.
__global__ void __launch_bounds__(256, 2) k_passA(const float* __restrict__ G,
                                                  const int* __restrict__ Pi) {
  __shared__ float s_y[8 * 1024];
  __shared__ float s_g[2048];
  __shared__ unsigned short s_pi[2048];
  const int tid = threadIdx.x;
  const size_t base = (size_t)blockIdx.x * 2048;

#pragma unroll
  for (int i = tid; i < 2048; i += 256) {
    s_g[i] = G[base + i];
    s_pi[i] = (unsigned short)(Pi[base + i] & 1023);
  }
#pragma unroll
  for (int i = tid; i < 8192; i += 256) s_y[i] = g_y[i];
  __syncthreads();

  const int w = tid >> 5, l = tid & 31;
  const float* yb = s_y + w * 1024;
  float e[64];
#pragma unroll
  for (int j = 0; j < 64; j++) {
    int i = j * 32 + l;
    e[j] = yb[s_pi[i]] * s_g[i];
  }
  wht_warp<64>(e, l);
  __half* o = g_work + (size_t)w * PADN + base;
#pragma unroll
  for (int j = 0; j < 64; j++) o[j * 32 + l] = __float2half_rn(e[j]);
}

// Pass B: stages h=2048..2^21 (2048-pt WHT across chunks, stride 2048).
// Tile = 2048 rows x 16 cols in smem (128 KB), 512 threads, warp per column.
// Transform = two register phases joined by an XOR-swizzled smem exchange
// (zero shuffles). Fused *S and truncation to OUTN on the way out.
// Swizzle: element (col c, row r) at tile[c*2048 + (r ^ ((r>>6)&31)) ^ ((c&8)<<1)]
__global__ void __launch_bounds__(512, 1) k_passB(const float* __restrict__ S,
                                                  float* __restrict__ out) {
  extern __shared__ float tile[];  // 16 * 2048 floats
  const int tid = threadIdx.x;
  const int b = blockIdx.y;
  const int c0 = blockIdx.x * 16;
  const __half* wrk = g_work + (size_t)b * PADN;

  // stage in: 2 lanes per row, 16B (8 halfs) each -> 32B coalesced per row
  for (int idx = tid; idx < 4096; idx += 512) {
    int r = idx >> 1;
    int part = (idx & 1) << 3;  // 0 or 8
    uint4 v = *(const uint4*)(wrk + (size_t)r * 2048 + c0 + part);
    const __half* hv = (const __half*)&v;
    int rs = (r ^ ((r >> 6) & 31)) ^ (part << 1);
#pragma unroll
    for (int m = 0; m < 8; m++)
      tile[(part + m) * 2048 + rs] = __half2float(hv[m]);
  }
  __syncthreads();

  const int w = tid >> 5, l = tid & 31;
  float* col = tile + w * 2048;
  const int cswz = (w & 8) << 1;
  float e[64];

  // phase 1: thread owns 64 contiguous rows [l*64, l*64+64): stages h=1..32
#pragma unroll
  for (int k = 0; k < 64; k++) e[k] = col[((l * 64 + k) ^ l) ^ cswz];
#pragma unroll
  for (int h = 1; h <= 32; h <<= 1) {
#pragma unroll
    for (int k = 0; k < 64; k++) {
      if ((k & h) == 0) {
        float a = e[k], bb = e[k | h];
        e[k] = a + bb;
        e[k | h] = a - bb;
      }
    }
  }
#pragma unroll
  for (int k = 0; k < 64; k++) col[((l * 64 + k) ^ l) ^ cswz] = e[k];
  __syncwarp();

  // phase 2: thread owns rows j*32+l: stages h=64..1024 (j-distance 2..32)
#pragma unroll
  for (int j = 0; j < 64; j++)
    e[j] = col[((j * 32 + l) ^ ((j >> 1) & 31)) ^ cswz];
#pragma unroll
  for (int d = 2; d <= 32; d <<= 1) {
#pragma unroll
    for (int j = 0; j < 64; j++) {
      if ((j & d) == 0) {
        float a = e[j], bb = e[j | d];
        e[j] = a + bb;
        e[j | d] = a - bb;
      }
    }
  }
#pragma unroll
  for (int j = 0; j < 64; j++)
    col[((j * 32 + l) ^ ((j >> 1) & 31)) ^ cswz] = e[j];
  __syncthreads();

  // stage out: thread handles a full row (16 cols = 64B), fused *S + truncation
  for (int r = tid; r < 2048; r += 512) {
    int rg = r ^ ((r >> 6) & 31);
    int kbase = r * 2048 + c0;
#pragma unroll
    for (int m4 = 0; m4 < 16; m4 += 4) {
      int k = kbase + m4;
      if (k < OUTN) {
        int sw = (m4 & 8) << 1;
        float4 s4 = *(const float4*)(S + k);
        float4 v;
        v.x = tile[(m4 + 0) * 2048 + (rg ^ sw)] * s4.x;
        v.y = tile[(m4 + 1) * 2048 + (rg ^ sw)] * s4.y;
        v.z = tile[(m4 + 2) * 2048 + (rg ^ sw)] * s4.z;
        v.w = tile[(m4 + 3) * 2048 + (rg ^ sw)] * s4.w;
        *(float4*)(out + (size_t)b * OUTN + k) = v;
      }
    }
  }
}

extern "C" void kernel_launch(void* const* d_in, const int* in_sizes, int n_in,
                              void* d_out, int out_size) {
  const float* x = (const float*)d_in[0];
  const float* B = (const float*)d_in[1];
  const float* G = (const float*)d_in[2];
  const float* S = (const float*)d_in[3];
  const int* Pi = (const int*)d_in[4];
  float* out = (float*)d_out;

  cudaFuncSetAttribute(k_passB, cudaFuncAttributeMaxDynamicSharedMemorySize,
                       131072);

  k_y<<<1, 256>>>(x, B);
  k_passA<<<2048, 256>>>(G, Pi);
  k_passB<<<dim3(128, 8), 512, 131072>>>(S, out);
}